// round 2
// baseline (speedup 1.0000x reference)
#include <cuda_runtime.h>
#include <math.h>

#define NN   100000
#define EE   1600000
#define HID  64
#define NL   5
#define NB   512
#define SCAN_T 512
#define SCAN_BLOCKS 196          /* ceil(100000/512); 196*512 = 100352 */

/* ------------------------------------------------------------------ */
/* device scratch (static __device__ arrays: allocation-free)          */
/* ------------------------------------------------------------------ */
__device__ float  g_h[NN * HID];
__device__ float  g_u[NN * HID];
__device__ float  g_t[NN * HID];
__device__ float  g_e[(size_t)EE * HID];      /* 409.6 MB, CSR order  */
__device__ int    g_deg[NN];
__device__ int    g_cur[NN];
__device__ int    g_incl[SCAN_BLOCKS * SCAN_T];
__device__ int    g_bsum[SCAN_BLOCKS];
__device__ int    g_off[NN + 1];
__device__ int    g_csr_src[EE];
__device__ int    g_csr_eid[EE];
__device__ double g_colsum[HID];
__device__ double g_colsq[HID];
__device__ float  g_scale[HID];
__device__ float  g_shift[HID];
__device__ float  g_gcnt[NB];

/* ------------------------------------------------------------------ */
/* packed f32x2 helpers (Blackwell FFMA2: 2x FMA throughput)           */
/* packed value carried as unsigned long long (asm "l" = 64-bit int)   */
/* ------------------------------------------------------------------ */
typedef unsigned long long pf2;

__device__ __forceinline__ pf2 pk2(float lo, float hi) {
    pf2 d;
    asm("mov.b64 %0, {%1, %2};" : "=l"(d)
        : "r"(__float_as_uint(lo)), "r"(__float_as_uint(hi)));
    return d;
}
__device__ __forceinline__ void upk2(pf2 d, float &lo, float &hi) {
    unsigned a, b;
    asm("mov.b64 {%0, %1}, %2;" : "=r"(a), "=r"(b) : "l"(d));
    lo = __uint_as_float(a); hi = __uint_as_float(b);
}
__device__ __forceinline__ pf2 fma2(pf2 a, pf2 b, pf2 c) {
    pf2 d;
    asm("fma.rn.f32x2 %0, %1, %2, %3;" : "=l"(d) : "l"(a), "l"(b), "l"(c));
    return d;
}

/* ------------------------------------------------------------------ */
/* CSR build                                                           */
/* ------------------------------------------------------------------ */
__global__ void k_zero2() {
    int i = blockIdx.x * blockDim.x + threadIdx.x;
    if (i < NN) { g_deg[i] = 0; g_cur[i] = 0; }
}

__global__ void k_hist(const int *__restrict__ ei) {
    int i = blockIdx.x * blockDim.x + threadIdx.x;
    if (i < EE) atomicAdd(&g_deg[ei[EE + i]], 1);
}

__global__ void k_scan_partial() {
    __shared__ int s[SCAN_T];
    int tid = threadIdx.x;
    int idx = blockIdx.x * SCAN_T + tid;
    int v = (idx < NN) ? g_deg[idx] : 0;
    s[tid] = v;
    __syncthreads();
#pragma unroll
    for (int d = 1; d < SCAN_T; d <<= 1) {
        int t = (tid >= d) ? s[tid - d] : 0;
        __syncthreads();
        s[tid] += t;
        __syncthreads();
    }
    g_incl[idx] = s[tid];
    if (tid == SCAN_T - 1) g_bsum[blockIdx.x] = s[tid];
}

__global__ void k_scan_bsum() {
    __shared__ int s[256];
    int tid = threadIdx.x;
    int v = (tid < SCAN_BLOCKS) ? g_bsum[tid] : 0;
    s[tid] = v;
    __syncthreads();
#pragma unroll
    for (int d = 1; d < 256; d <<= 1) {
        int t = (tid >= d) ? s[tid - d] : 0;
        __syncthreads();
        s[tid] += t;
        __syncthreads();
    }
    if (tid < SCAN_BLOCKS) g_bsum[tid] = s[tid] - v;   /* exclusive */
}

__global__ void k_scan_add() {
    int i = blockIdx.x * blockDim.x + threadIdx.x;
    if (i <= NN)
        g_off[i] = (i == 0) ? 0 : g_incl[i - 1] + g_bsum[(i - 1) >> 9];
}

__global__ void k_scatter(const int *__restrict__ ei) {
    int i = blockIdx.x * blockDim.x + threadIdx.x;
    if (i < EE) {
        int d = ei[EE + i];
        int p = g_off[d] + atomicAdd(&g_cur[d], 1);
        g_csr_src[p] = ei[i];
        g_csr_eid[p] = i;
    }
}

/* ------------------------------------------------------------------ */
/* edge projection: e = edge_attr @ edge_W + edge_b, stored CSR-order  */
/* one warp per CSR slot; lane computes outputs (lane, lane+32)        */
/* ------------------------------------------------------------------ */
__global__ void k_edgeproj(const float *__restrict__ ea,
                           const float *__restrict__ W,
                           const float *__restrict__ b) {
    __shared__ float sW[16 * 64];
    __shared__ float sB[64];
    int tid = threadIdx.x;
#pragma unroll
    for (int i = tid; i < 16 * 64; i += 256) sW[i] = W[i];
    if (tid < 64) sB[tid] = b[tid];
    __syncthreads();

    int gw = blockIdx.x * 8 + (tid >> 5);
    if (gw >= EE) return;
    int lane = tid & 31;
    int eid = g_csr_eid[gw];
    const float *a = ea + (size_t)eid * 16;

    pf2 acc = pk2(sB[lane], sB[lane + 32]);
#pragma unroll
    for (int d = 0; d < 16; d++) {
        float av = __ldg(a + d);
        pf2 wd = pk2(sW[d * 64 + lane], sW[d * 64 + lane + 32]);
        acc = fma2(pk2(av, av), wd, acc);
    }
    float e0, e1;
    upk2(acc, e0, e1);
    g_e[(size_t)gw * 64 + lane]      = e0;
    g_e[(size_t)gw * 64 + lane + 32] = e1;
}

/* ------------------------------------------------------------------ */
/* aggregation: u[v] = (1+eps)*h[v] + sum_{e->v} relu(h[src] + e)      */
/* one warp per node, lane owns feature pair (2*lane, 2*lane+1)        */
/* block 0 additionally zeroes the BN stat accumulators                */
/* ------------------------------------------------------------------ */
__global__ void k_aggr(const float *__restrict__ eps_arr, int l) {
    if (blockIdx.x == 0) {
        int t = threadIdx.x;
        if (t < 64)                g_colsum[t]      = 0.0;
        else if (t < 128)          g_colsq[t - 64]  = 0.0;
    }
    int v = blockIdx.x * 8 + (threadIdx.x >> 5);
    if (v >= NN) return;
    int lane = threadIdx.x & 31;
    int f0 = lane * 2;
    float ep = 1.0f + eps_arr[l];

    float2 hv = *(const float2 *)(g_h + (size_t)v * 64 + f0);
    float ax = ep * hv.x, ay = ep * hv.y;

    int beg = g_off[v], end = g_off[v + 1];
    for (int p = beg; p < end; p++) {
        int s = g_csr_src[p];
        float2 hs = *(const float2 *)(g_h + (size_t)s * 64 + f0);
        float2 ev = *(const float2 *)(g_e + (size_t)p * 64 + f0);
        ax += fmaxf(hs.x + ev.x, 0.0f);
        ay += fmaxf(hs.y + ev.y, 0.0f);
    }
    float2 o; o.x = ax; o.y = ay;
    *(float2 *)(g_u + (size_t)v * 64 + f0) = o;
}

/* ------------------------------------------------------------------ */
/* fused linear chain: out = L_{n-1}(relu(...relu(L_0(in))...))        */
/* 128-row tile/block, 256 threads, thread = 8 rows x 4 cols,          */
/* packed f32x2 FMA; optional BN stat accumulation on final output     */
/* ------------------------------------------------------------------ */
#define SMEM_LIN ((8192 + 8192 + 4096 + 64 + 1024 + 1024) * 4)   /* 90368 B */

__global__ void __launch_bounds__(256, 2)
k_fused_linear(const float *__restrict__ in, float *__restrict__ out,
               const float *__restrict__ Wb, const float *__restrict__ bb,
               int M, int nstages, int do_stats) {
    extern __shared__ float smem[];
    float *sA0 = smem;                 /* 128*64 */
    float *sA1 = sA0 + 128 * 64;       /* 128*64 */
    float *sW  = sA1 + 128 * 64;       /* 64*64  */
    float *sB  = sW + 64 * 64;         /* 64     */
    float *sPs = sB + 64;              /* 16*64  */
    float *sPq = sPs + 16 * 64;        /* 16*64  */

    int tid = threadIdx.x;
    int m0 = blockIdx.x * 128;

    /* load input tile (zero-pad tail rows) */
    for (int i = tid; i < 128 * 16; i += 256) {
        int r = i >> 4, q = i & 15;
        float4 v = make_float4(0.f, 0.f, 0.f, 0.f);
        if (m0 + r < M)
            v = *(const float4 *)(in + (size_t)(m0 + r) * 64 + q * 4);
        *(float4 *)(sA0 + r * 64 + q * 4) = v;
    }

    int tx = tid & 15, ty = tid >> 4;
    int r0 = ty * 8, c0 = tx * 4;

    for (int stage = 0; stage < nstages; stage++) {
        __syncthreads();   /* prior reads of sW / act writes visible */
        const float *Ws = Wb + (size_t)stage * 64 * 64;
        for (int i = tid; i < 1024; i += 256)
            ((float4 *)sW)[i] = ((const float4 *)Ws)[i];
        if (tid < 16)
            ((float4 *)sB)[tid] = ((const float4 *)(bb + stage * 64))[tid];
        __syncthreads();

        float *sIn  = (stage & 1) ? sA1 : sA0;
        float *sOut = (stage & 1) ? sA0 : sA1;

        pf2 acc[8][2];
#pragma unroll
        for (int i = 0; i < 8; i++) { acc[i][0] = 0ull; acc[i][1] = 0ull; }

#pragma unroll
        for (int kk = 0; kk < 64; kk += 4) {
            float4 a[8];
#pragma unroll
            for (int i = 0; i < 8; i++)
                a[i] = *(const float4 *)(sIn + (r0 + i) * 64 + kk);
#pragma unroll
            for (int k4 = 0; k4 < 4; k4++) {
                float4 w = *(const float4 *)(sW + (kk + k4) * 64 + c0);
                pf2 w01 = pk2(w.x, w.y), w23 = pk2(w.z, w.w);
#pragma unroll
                for (int i = 0; i < 8; i++) {
                    float av = (k4 == 0) ? a[i].x : (k4 == 1) ? a[i].y
                             : (k4 == 2) ? a[i].z : a[i].w;
                    pf2 ad = pk2(av, av);
                    acc[i][0] = fma2(ad, w01, acc[i][0]);
                    acc[i][1] = fma2(ad, w23, acc[i][1]);
                }
            }
        }

        float bx = sB[c0], by = sB[c0 + 1], bz = sB[c0 + 2], bw = sB[c0 + 3];
        bool relu = (stage < nstages - 1);
        float o[8][4];
#pragma unroll
        for (int i = 0; i < 8; i++) {
            float x0, x1, x2, x3;
            upk2(acc[i][0], x0, x1);
            upk2(acc[i][1], x2, x3);
            x0 += bx; x1 += by; x2 += bz; x3 += bw;
            if (relu) {
                x0 = fmaxf(x0, 0.f); x1 = fmaxf(x1, 0.f);
                x2 = fmaxf(x2, 0.f); x3 = fmaxf(x3, 0.f);
            }
            o[i][0] = x0; o[i][1] = x1; o[i][2] = x2; o[i][3] = x3;
        }

        if (stage < nstages - 1) {
#pragma unroll
            for (int i = 0; i < 8; i++)
                *(float4 *)(sOut + (r0 + i) * 64 + c0) =
                    make_float4(o[i][0], o[i][1], o[i][2], o[i][3]);
        } else {
#pragma unroll
            for (int i = 0; i < 8; i++)
                if (m0 + r0 + i < M)
                    *(float4 *)(out + (size_t)(m0 + r0 + i) * 64 + c0) =
                        make_float4(o[i][0], o[i][1], o[i][2], o[i][3]);
            if (do_stats) {
                float ps[4] = {0, 0, 0, 0}, pq[4] = {0, 0, 0, 0};
#pragma unroll
                for (int i = 0; i < 8; i++)
                    if (m0 + r0 + i < M)
#pragma unroll
                        for (int j = 0; j < 4; j++) {
                            ps[j] += o[i][j];
                            pq[j] += o[i][j] * o[i][j];
                        }
#pragma unroll
                for (int j = 0; j < 4; j++) {
                    sPs[ty * 64 + c0 + j] = ps[j];
                    sPq[ty * 64 + c0 + j] = pq[j];
                }
                __syncthreads();
                if (tid < 64) {
                    float S = 0.f, Q = 0.f;
#pragma unroll
                    for (int g = 0; g < 16; g++) {
                        S += sPs[g * 64 + tid];
                        Q += sPq[g * 64 + tid];
                    }
                    atomicAdd(&g_colsum[tid], (double)S);
                    atomicAdd(&g_colsq[tid], (double)Q);
                }
            }
        }
    }
}

/* ------------------------------------------------------------------ */
/* BN finalize + apply (relu + residual)                               */
/* ------------------------------------------------------------------ */
__global__ void k_bn_finalize(const float *__restrict__ gamma,
                              const float *__restrict__ beta, int l) {
    int c = threadIdx.x;
    if (c < HID) {
        double mu  = g_colsum[c] / (double)NN;
        double var = g_colsq[c] / (double)NN - mu * mu;
        float s = (float)(1.0 / sqrt(var + 1e-5)) * gamma[l * HID + c];
        g_scale[c] = s;
        g_shift[c] = beta[l * HID + c] - (float)mu * s;
    }
}

__global__ void k_apply() {
    __shared__ float ss[64], sh[64];
    int tid = threadIdx.x;
    if (tid < 64) { ss[tid] = g_scale[tid]; sh[tid] = g_shift[tid]; }
    __syncthreads();
    int i = blockIdx.x * blockDim.x + tid;
    if (i < NN * 16) {
        int c = (i & 15) * 4;
        float4 t = ((const float4 *)g_t)[i];
        float4 h = ((const float4 *)g_h)[i];
        float4 r;
        r.x = fmaxf(fmaf(t.x, ss[c + 0], sh[c + 0]), 0.f) + h.x;
        r.y = fmaxf(fmaf(t.y, ss[c + 1], sh[c + 1]), 0.f) + h.y;
        r.z = fmaxf(fmaf(t.z, ss[c + 2], sh[c + 2]), 0.f) + h.z;
        r.w = fmaxf(fmaf(t.w, ss[c + 3], sh[c + 3]), 0.f) + h.w;
        ((float4 *)g_h)[i] = r;
    }
}

/* ------------------------------------------------------------------ */
/* global mean pool over batch (sorted) via atomics                    */
/* ------------------------------------------------------------------ */
__global__ void k_pool_zero(float *__restrict__ out) {
    int i = blockIdx.x * blockDim.x + threadIdx.x;
    if (i < NB * HID) out[i] = 0.f;
    if (i < NB) g_gcnt[i] = 0.f;
}

__global__ void k_pool_sum(const int *__restrict__ batch,
                           float *__restrict__ out) {
    int v = blockIdx.x * 8 + (threadIdx.x >> 5);
    if (v >= NN) return;
    int lane = threadIdx.x & 31;
    int f0 = lane * 2;
    int b = batch[v];
    float2 hv = *(const float2 *)(g_h + (size_t)v * 64 + f0);
    atomicAdd(&out[b * 64 + f0], hv.x);
    atomicAdd(&out[b * 64 + f0 + 1], hv.y);
    if (lane == 0) atomicAdd(&g_gcnt[b], 1.0f);
}

__global__ void k_pool_div(float *__restrict__ out) {
    int i = blockIdx.x * blockDim.x + threadIdx.x;
    if (i < NB * HID) out[i] /= fmaxf(g_gcnt[i >> 6], 1.0f);
}

/* ------------------------------------------------------------------ */
/* launch                                                              */
/* ------------------------------------------------------------------ */
extern "C" void kernel_launch(void *const *d_in, const int *in_sizes, int n_in,
                              void *d_out, int out_size) {
    const float *x         = (const float *)d_in[0];
    const float *edge_attr = (const float *)d_in[1];
    const float *node_W    = (const float *)d_in[2];
    const float *node_b    = (const float *)d_in[3];
    const float *edge_W    = (const float *)d_in[4];
    const float *edge_b    = (const float *)d_in[5];
    const float *eps_arr   = (const float *)d_in[6];
    const float *mlp_W     = (const float *)d_in[7];
    const float *mlp_b     = (const float *)d_in[8];
    const float *bn_gamma  = (const float *)d_in[9];
    const float *bn_beta   = (const float *)d_in[10];
    const int   *edge_index = (const int *)d_in[11];
    const int   *batch      = (const int *)d_in[12];
    float *out = (float *)d_out;

    cudaFuncSetAttribute(k_fused_linear,
                         cudaFuncAttributeMaxDynamicSharedMemorySize, SMEM_LIN);

    float *ph, *pu, *pt;
    cudaGetSymbolAddress((void **)&ph, g_h);
    cudaGetSymbolAddress((void **)&pu, g_u);
    cudaGetSymbolAddress((void **)&pt, g_t);

    const int LIN_BLOCKS = (NN + 127) / 128;       /* 782   */
    const int WARP8      = (NN + 7) / 8;           /* 12500 */

    /* ---- preprocessing ---- */
    k_zero2<<<(NN + 255) / 256, 256>>>();
    k_hist<<<(EE + 255) / 256, 256>>>(edge_index);
    k_scan_partial<<<SCAN_BLOCKS, SCAN_T>>>();
    k_scan_bsum<<<1, 256>>>();
    k_scan_add<<<(NN + 256) / 256, 256>>>();
    k_scatter<<<(EE + 255) / 256, 256>>>(edge_index);
    k_edgeproj<<<EE / 8, 256>>>(edge_attr, edge_W, edge_b);

    /* node projection: h = x @ node_W + node_b */
    k_fused_linear<<<LIN_BLOCKS, 256, SMEM_LIN>>>(x, ph, node_W, node_b,
                                                  NN, 1, 0);

    /* ---- layers ---- */
    for (int l = 0; l < NL; l++) {
        k_aggr<<<WARP8, 256>>>(eps_arr, l);
        k_fused_linear<<<LIN_BLOCKS, 256, SMEM_LIN>>>(
            pu, pt, mlp_W + (size_t)l * 4 * 64 * 64, mlp_b + (size_t)l * 4 * 64,
            NN, 4, 1);
        k_bn_finalize<<<1, 64>>>(bn_gamma, bn_beta, l);
        k_apply<<<(NN * 16 + 255) / 256, 256>>>();
    }

    /* ---- pooling ---- */
    k_pool_zero<<<(NB * HID + 255) / 256, 256>>>(out);
    k_pool_sum<<<WARP8, 256>>>(batch, out);
    k_pool_div<<<(NB * HID + 255) / 256, 256>>>(out);
}